// round 9
// baseline (speedup 1.0000x reference)
#include <cuda_runtime.h>
#include <cstdint>

// ---------------- problem constants ----------------
#define NB 4
#define NS 4096
#define NDIN 2048
#define NDOUT 2048
#define NR 16
#define NE 12
#define NM (NB * NS)  // 16384

// ---------------- GEMM tiling ----------------
#define BM 128
#define BN 128
#define CK 16                    // K per chunk (tf32): 64B rows
#define NCHUNK (NDIN / CK)       // 128
#define NCHTOT (NCHUNK + 1)      // +1 LoRA chunk (K=16 exactly)
#define NSTAGE 4

#define PART_SZ 8192                         // 128 rows x 64B
#define OF_B PART_SZ
#define STAGE_SZ (2 * PART_SZ)               // 16384
#define SMEM_TOTAL (NSTAGE * STAGE_SZ)       // 65536 (x3 CTAs = 192KB/SM)

// ---------------- scratch (device globals: allocation-free rule) ----------------
__device__ __align__(16) float g_xt[(size_t)NM * NDIN];          // tf32(x)
__device__ __align__(16) float g_wt[(size_t)NDOUT * NDIN];       // tf32(W_org)
__device__ __align__(16) float g_lxt[(size_t)NM * 16];           // tf32(lx)
__device__ __align__(16) float g_cbt[(size_t)NB * NDOUT * 16];   // tf32(comb)

// ---------------- PTX helpers (plain sm_80+ instructions only) ----------------
__device__ __forceinline__ uint32_t smem_u32(const void* p) {
    uint32_t a;
    asm("{ .reg .u64 t; cvta.to.shared.u64 t, %1; cvt.u32.u64 %0, t; }" : "=r"(a) : "l"(p));
    return a;
}
__device__ __forceinline__ uint32_t f2tf(float v) {
    uint32_t o;
    asm("cvt.rna.tf32.f32 %0, %1;" : "=r"(o) : "f"(v));
    return o;
}
__device__ __forceinline__ void cp16(uint32_t saddr, const void* gptr) {
    asm volatile("cp.async.cg.shared.global [%0], [%1], 16;"
                 :: "r"(saddr), "l"(__cvta_generic_to_global(gptr)) : "memory");
}
__device__ __forceinline__ void cp_commit() {
    asm volatile("cp.async.commit_group;" ::: "memory");
}
__device__ __forceinline__ void cp_wait2() {
    asm volatile("cp.async.wait_group 2;" ::: "memory");
}
__device__ __forceinline__ void cp_wait1() {
    asm volatile("cp.async.wait_group 1;" ::: "memory");
}
#define LDSM4(r0, r1, r2, r3, addr)                                              \
    asm volatile("ldmatrix.sync.aligned.m8n8.x4.shared.b16 {%0,%1,%2,%3}, [%4];" \
                 : "=r"(r0), "=r"(r1), "=r"(r2), "=r"(r3) : "r"(addr))
#define MMATF32(c, a, b0, b1)                                                 \
    asm volatile("mma.sync.aligned.m16n8k8.row.col.f32.tf32.tf32.f32 "        \
                 "{%0,%1,%2,%3},{%4,%5,%6,%7},{%8,%9},{%0,%1,%2,%3};"         \
                 : "+f"((c)[0]), "+f"((c)[1]), "+f"((c)[2]), "+f"((c)[3])     \
                 : "r"((a)[0]), "r"((a)[1]), "r"((a)[2]), "r"((a)[3]),        \
                   "r"(b0), "r"(b1))

// 64B-row swizzle: 16B-chunk' = ch ^ ((row>>1)&3)  (validated R7)
__device__ __forceinline__ uint32_t swof(int row, int ch) {
    return (uint32_t)(row * 64 + ((ch ^ ((row >> 1) & 3)) << 4));
}

// ---------------- pre-kernels: tf32 round-to-nearest conversion ----------------
__device__ __forceinline__ void cvt8(const float* src, float* dst, size_t i) {
    float4 v0 = *(const float4*)(src + i);
    float4 v1 = *(const float4*)(src + i + 4);
    uint4 o0 = make_uint4(f2tf(v0.x), f2tf(v0.y), f2tf(v0.z), f2tf(v0.w));
    uint4 o1 = make_uint4(f2tf(v1.x), f2tf(v1.y), f2tf(v1.z), f2tf(v1.w));
    *(uint4*)(dst + i) = o0;
    *(uint4*)(dst + i + 4) = o1;
}
__global__ void k_cvt_x(const float* __restrict__ x) {
    size_t i = ((size_t)blockIdx.x * 256 + threadIdx.x) * 8;
    cvt8(x, g_xt, i);
}
__global__ void k_cvt_w_comb(const float* __restrict__ W_org,
                             const float* __restrict__ gate,
                             const float* __restrict__ W_up) {
    if (blockIdx.x < 2048) {
        size_t i = ((size_t)blockIdx.x * 256 + threadIdx.x) * 8;
        cvt8(W_org, g_wt, i);
    } else {
        int idx = (blockIdx.x - 2048) * 256 + threadIdx.x;
        if (idx >= NB * NDOUT * NR) return;
        int b = idx / (NDOUT * NR);
        int orr = idx - b * (NDOUT * NR);
        int o = orr >> 4, r = orr & 15;
        float s = 0.f;
#pragma unroll
        for (int e = 0; e < NE; e++)
            s += __ldg(&gate[b * NE + e]) * __ldg(&W_up[(size_t)e * NDOUT * NR + orr]);
        g_cbt[((size_t)b * NDOUT + o) * 16 + r] = __uint_as_float(f2tf(s));
    }
}

// ---------------- k_lx: lx[m,0:16] = x @ W_down^T via tf32 mma ----------------
#define LXW 131072                       // 16 n-rows x 2048 k x 4B (tf32 W_down)
#define LX_STG 16384                     // 128 rows x 32 k x 4B
#define LX_SMEM (LXW + 3 * LX_STG)       // 180224
#define LXCK 32

__device__ __forceinline__ uint32_t lx_swof(int row, int ch) {   // 128B rows
    return (uint32_t)(row * 128 + ((ch ^ (row & 7)) << 4));
}
__device__ __forceinline__ void lx_issue(uint32_t sb, int s, int c, int rowBase, int tid) {
    uint32_t xs = sb + LXW + s * LX_STG;
#pragma unroll
    for (int j = 0; j < 8; j++) {
        int g = tid + 128 * j;
        int row = g >> 3, ch = g & 7;
        cp16(xs + lx_swof(row, ch), g_xt + (size_t)(rowBase + row) * NDIN + c * LXCK + ch * 4);
    }
}

__global__ void __launch_bounds__(128, 1) k_lx(const float* __restrict__ Wd) {
    extern __shared__ char sm[];
    const uint32_t sb = smem_u32(sm);
    const int tid = threadIdx.x;
    const int w = tid >> 5, lane = tid & 31;
    const int rowBase = blockIdx.x * 128;
    const int lane7 = lane & 7, half = (lane >> 3) & 1, kh = lane >> 4;

    for (int idx = tid; idx < 16 * 512; idx += 128) {
        int n = idx >> 9, ch = idx & 511;
        float4 v = *(const float4*)(Wd + (size_t)n * NDIN + ch * 4);
        uint4 o = make_uint4(f2tf(v.x), f2tf(v.y), f2tf(v.z), f2tf(v.w));
        *(uint4*)(sm + n * 8192 + ((ch ^ (n & 7)) << 4)) = o;
    }

    float acc[2][2][4];
#pragma unroll
    for (int i = 0; i < 2; i++)
#pragma unroll
        for (int j = 0; j < 2; j++)
#pragma unroll
            for (int q = 0; q < 4; q++) acc[i][j][q] = 0.f;

    lx_issue(sb, 0, 0, rowBase, tid); cp_commit();
    lx_issue(sb, 1, 1, rowBase, tid); cp_commit();

    uint32_t aRow[2], aSw[2];
#pragma unroll
    for (int mt = 0; mt < 2; mt++) {
        int r = w * 32 + mt * 16 + half * 8 + lane7;
        aRow[mt] = (uint32_t)r * 128; aSw[mt] = (uint32_t)(r & 7);
    }
    const int rB = half * 8 + lane7;
    const uint32_t bOff = (uint32_t)rB * 8192, bSw = (uint32_t)(rB & 7);

    for (int c = 0; c < NDIN / LXCK; c++) {
        cp_wait1();
        __syncthreads();
        if (c + 2 < NDIN / LXCK) lx_issue(sb, (c + 2) % 3, c + 2, rowBase, tid);
        cp_commit();
        const uint32_t xs = sb + LXW + (c % 3) * LX_STG;
#pragma unroll
        for (int ks = 0; ks < 4; ks++) {
            uint32_t chB = (uint32_t)(((c * 4 + ks) << 1) | kh);
            uint32_t r0, r1, r2, r3;
            LDSM4(r0, r1, r2, r3, sb + bOff + ((chB ^ bSw) << 4));
            uint32_t bf0[2] = {r0, r2}, bf1[2] = {r1, r3};
#pragma unroll
            for (int mt = 0; mt < 2; mt++) {
                uint32_t a[4];
                uint32_t ch = (uint32_t)((ks << 1) | kh);
                LDSM4(a[0], a[1], a[2], a[3], xs + aRow[mt] + ((ch ^ aSw[mt]) << 4));
                MMATF32(acc[mt][0], a, bf0[0], bf0[1]);
                MMATF32(acc[mt][1], a, bf1[0], bf1[1]);
            }
        }
        __syncthreads();
    }

#pragma unroll
    for (int mt = 0; mt < 2; mt++) {
        int row = rowBase + w * 32 + mt * 16 + (lane >> 2);
#pragma unroll
        for (int nt = 0; nt < 2; nt++) {
            int col = nt * 8 + (lane & 3) * 2;
            g_lxt[(size_t)row * 16 + col]           = __uint_as_float(f2tf(acc[mt][nt][0]));
            g_lxt[(size_t)row * 16 + col + 1]       = __uint_as_float(f2tf(acc[mt][nt][1]));
            g_lxt[(size_t)(row + 8) * 16 + col]     = __uint_as_float(f2tf(acc[mt][nt][2]));
            g_lxt[(size_t)(row + 8) * 16 + col + 1] = __uint_as_float(f2tf(acc[mt][nt][3]));
        }
    }
}

// ---------------- main GEMM: tf32, 128x128 CTA, 64x64 warp tiles ----------------
__global__ void __launch_bounds__(128, 3) k_gemm(float* __restrict__ out) {
    extern __shared__ char smem[];
    const uint32_t sb0 = smem_u32(smem);
    const int tid = threadIdx.x;
    const int wid = tid >> 5, lane = tid & 31;
    const int wm = wid >> 1, wn = wid & 1;      // 2x2 warp grid, warp tile 64x64
    const int rowBase = blockIdx.y * BM;
    const int colBase = blockIdx.x * BN;
    const int b = blockIdx.y >> 5;              // NS/BM = 32 row-blocks per batch
    const int lane7 = lane & 7, half = (lane >> 3) & 1, kh = lane >> 4;

    // fragment address bases (swizzle folded; mt/bp advance = +1024B, ks via XOR)
    uint32_t aOff0, bOff0;
    {
        int ra = wm * 64 + half * 8 + lane7;
        aOff0 = (uint32_t)(ra * 64 + (((ra >> 1) & 3) << 4));
        int rb = wn * 64 + half * 8 + lane7;
        bOff0 = OF_B + (uint32_t)(rb * 64 + (((rb >> 1) & 3) << 4));
    }

    // loader state: 4 A + 4 B cp16 per chunk, j-stride 2048B smem / 32 rows global
    const int lrow = tid >> 2, lch = tid & 3;
    const uint32_t so0 = swof(lrow, lch);
    const float* aG = g_xt + (size_t)rowBase * NDIN + (size_t)lrow * NDIN + lch * 4;
    const float* bG = g_wt + (size_t)colBase * NDIN + (size_t)lrow * NDIN + lch * 4;
    const float* aL = g_lxt + (size_t)(rowBase + lrow) * 16 + lch * 4;
    const float* bL = g_cbt + ((size_t)b * NDOUT + colBase + lrow) * 16 + lch * 4;

    float acc[4][8][4];
#pragma unroll
    for (int i = 0; i < 4; i++)
#pragma unroll
        for (int j = 0; j < 8; j++)
#pragma unroll
            for (int q = 0; q < 4; q++) acc[i][j][q] = 0.f;

#pragma unroll
    for (int p = 0; p < 3; p++) {   // prologue: chunks 0,1,2
        uint32_t s = sb0 + p * STAGE_SZ;
#pragma unroll
        for (int j = 0; j < 4; j++) {
            cp16(s + so0 + j * 2048, aG + p * CK + (size_t)j * 32 * NDIN);
            cp16(s + OF_B + so0 + j * 2048, bG + p * CK + (size_t)j * 32 * NDIN);
        }
        cp_commit();
    }

    for (int kc = 0; kc < NCHTOT; kc++) {
        cp_wait2();
        __syncthreads();   // chunk kc ready; all warps done with chunk kc-1's slot

        const int nk = kc + 3;
        if (nk < NCHTOT) {
            uint32_t s = sb0 + (nk & 3) * STAGE_SZ;
            if (nk < NCHUNK) {
#pragma unroll
                for (int j = 0; j < 4; j++) {
                    cp16(s + so0 + j * 2048, aG + nk * CK + (size_t)j * 32 * NDIN);
                    cp16(s + OF_B + so0 + j * 2048, bG + nk * CK + (size_t)j * 32 * NDIN);
                }
            } else {  // LoRA chunk: row stride 16 floats = 64B
#pragma unroll
                for (int j = 0; j < 4; j++) {
                    cp16(s + so0 + j * 2048, aL + (size_t)j * 32 * 16);
                    cp16(s + OF_B + so0 + j * 2048, bL + (size_t)j * 32 * 16);
                }
            }
        }
        cp_commit();

        const uint32_t Sb = sb0 + (kc & 3) * STAGE_SZ;
#pragma unroll
        for (int ks = 0; ks < 2; ks++) {
            const uint32_t cx = (uint32_t)((ks << 1) | kh) << 4;
            // B fragments: 8 n-tiles via 4 LDSM.x4
            uint32_t bf[8][2];
#pragma unroll
            for (int bp = 0; bp < 4; bp++) {
                uint32_t r0, r1, r2, r3;
                LDSM4(r0, r1, r2, r3, Sb + ((bOff0 + bp * 1024) ^ cx));
                bf[bp * 2 + 0][0] = r0; bf[bp * 2 + 0][1] = r2;
                bf[bp * 2 + 1][0] = r1; bf[bp * 2 + 1][1] = r3;
            }
            uint32_t a[2][4];
            LDSM4(a[0][0], a[0][1], a[0][2], a[0][3], Sb + (aOff0 ^ cx));
#pragma unroll
            for (int mt = 0; mt < 4; mt++) {
                if (mt < 3) {
                    uint32_t* an = a[(mt + 1) & 1];
                    LDSM4(an[0], an[1], an[2], an[3],
                          Sb + ((aOff0 + (mt + 1) * 1024) ^ cx));
                }
                const uint32_t* ac = a[mt & 1];
#pragma unroll
                for (int nt = 0; nt < 8; nt++)
                    MMATF32(acc[mt][nt], ac, bf[nt][0], bf[nt][1]);
            }
        }
    }

    // ---------------- epilogue ----------------
#pragma unroll
    for (int mt = 0; mt < 4; mt++) {
#pragma unroll
        for (int nt = 0; nt < 8; nt++) {
            int row = rowBase + wm * 64 + mt * 16 + (lane >> 2);
            int col = colBase + wn * 64 + nt * 8 + (lane & 3) * 2;
            *(float2*)&out[(size_t)row * NDOUT + col] =
                make_float2(acc[mt][nt][0], acc[mt][nt][1]);
            *(float2*)&out[(size_t)(row + 8) * NDOUT + col] =
                make_float2(acc[mt][nt][2], acc[mt][nt][3]);
        }
    }
}

// ---------------- launch ----------------
extern "C" void kernel_launch(void* const* d_in, const int* in_sizes, int n_in,
                              void* d_out, int out_size) {
    const float* x      = (const float*)d_in[0];
    const float* gate   = (const float*)d_in[1];
    const float* W_org  = (const float*)d_in[2];
    const float* W_down = (const float*)d_in[3];
    const float* W_up   = (const float*)d_in[4];
    float* out = (float*)d_out;

    cudaFuncSetAttribute(k_gemm, cudaFuncAttributeMaxDynamicSharedMemorySize, SMEM_TOTAL);
    cudaFuncSetAttribute(k_lx, cudaFuncAttributeMaxDynamicSharedMemorySize, LX_SMEM);

    k_cvt_x<<<(size_t)NM * NDIN / 2048, 256>>>(x);
    k_cvt_w_comb<<<2048 + 512, 256>>>(W_org, gate, W_up);
    k_lx<<<NM / 128, 128, LX_SMEM>>>(W_down);

    dim3 grid(NDOUT / BN, NM / BM);   // (16, 128) = 2048 CTAs
    k_gemm<<<grid, 128, SMEM_TOTAL>>>(out);
}

// round 10
// speedup vs baseline: 1.8446x; 1.8446x over previous
#include <cuda_runtime.h>
#include <cuda_fp16.h>
#include <cstdint>

// ---------------- problem constants ----------------
#define NB 4
#define NS 4096
#define NDIN 2048
#define NDOUT 2048
#define NR 16
#define NE 12
#define NM (NB * NS)  // 16384

// ---------------- GEMM tiling ----------------
#define BM 128
#define BN 128
#define CK 32                    // K per chunk (fp16): 64B rows
#define NCHUNK (NDIN / CK)       // 64
#define NCHTOT (NCHUNK + 1)      // +1 LoRA chunk (K=16 zero-padded to 32)
#define NSTAGE 4

#define PART_SZ 8192                         // 128 rows x 64B
#define OF_B PART_SZ
#define STAGE_SZ (2 * PART_SZ)               // 16384
#define SMEM_TOTAL (NSTAGE * STAGE_SZ)       // 65536 (x3 CTAs = 192KB/SM)

// ---------------- scratch (device globals: allocation-free rule) ----------------
__device__ __align__(16) __half g_x16[(size_t)NM * NDIN];
__device__ __align__(16) __half g_w16[(size_t)NDOUT * NDIN];
__device__ __align__(16) __half g_lx16[(size_t)NM * 32];          // cols 16-31 = 0
__device__ __align__(16) __half g_cb16[(size_t)NB * NDOUT * 32];  // cols 16-31 = 0

// ---------------- PTX helpers (plain sm_80+ instructions only) ----------------
__device__ __forceinline__ uint32_t smem_u32(const void* p) {
    uint32_t a;
    asm("{ .reg .u64 t; cvta.to.shared.u64 t, %1; cvt.u32.u64 %0, t; }" : "=r"(a) : "l"(p));
    return a;
}
__device__ __forceinline__ void cp16(uint32_t saddr, const void* gptr) {
    asm volatile("cp.async.cg.shared.global [%0], [%1], 16;"
                 :: "r"(saddr), "l"(__cvta_generic_to_global(gptr)) : "memory");
}
__device__ __forceinline__ void cp_commit() {
    asm volatile("cp.async.commit_group;" ::: "memory");
}
__device__ __forceinline__ void cp_wait2() {
    asm volatile("cp.async.wait_group 2;" ::: "memory");
}
__device__ __forceinline__ void cp_wait1() {
    asm volatile("cp.async.wait_group 1;" ::: "memory");
}
#define LDSM4(r0, r1, r2, r3, addr)                                              \
    asm volatile("ldmatrix.sync.aligned.m8n8.x4.shared.b16 {%0,%1,%2,%3}, [%4];" \
                 : "=r"(r0), "=r"(r1), "=r"(r2), "=r"(r3) : "r"(addr))
#define MMAF16(c, a, b0, b1)                                                  \
    asm volatile("mma.sync.aligned.m16n8k16.row.col.f32.f16.f16.f32 "         \
                 "{%0,%1,%2,%3},{%4,%5,%6,%7},{%8,%9},{%0,%1,%2,%3};"         \
                 : "+f"((c)[0]), "+f"((c)[1]), "+f"((c)[2]), "+f"((c)[3])     \
                 : "r"((a)[0]), "r"((a)[1]), "r"((a)[2]), "r"((a)[3]),        \
                   "r"(b0), "r"(b1))

// 64B-row swizzle (validated R7/R9): 16B-chunk' = ch ^ ((row>>1)&3)
__device__ __forceinline__ uint32_t swof(int row, int ch) {
    return (uint32_t)(row * 64 + ((ch ^ ((row >> 1) & 3)) << 4));
}

// ---------------- pre-kernels: fp32 -> fp16 RN conversion ----------------
union H8 { __half2 h[4]; uint4 u; };

__device__ __forceinline__ void cvt8h(const float* src, __half* dst, size_t i) {
    float4 v0 = *(const float4*)(src + i);
    float4 v1 = *(const float4*)(src + i + 4);
    H8 o;
    o.h[0] = __float22half2_rn(make_float2(v0.x, v0.y));
    o.h[1] = __float22half2_rn(make_float2(v0.z, v0.w));
    o.h[2] = __float22half2_rn(make_float2(v1.x, v1.y));
    o.h[3] = __float22half2_rn(make_float2(v1.z, v1.w));
    *(uint4*)(dst + i) = o.u;
}
__global__ void k_cvt_x(const float* __restrict__ x) {
    size_t i = ((size_t)blockIdx.x * 256 + threadIdx.x) * 8;
    cvt8h(x, g_x16, i);
}
__global__ void k_cvt_w_comb(const float* __restrict__ W_org,
                             const float* __restrict__ gate,
                             const float* __restrict__ W_up) {
    if (blockIdx.x < 2048) {
        size_t i = ((size_t)blockIdx.x * 256 + threadIdx.x) * 8;
        cvt8h(W_org, g_w16, i);
    } else {
        int idx = (blockIdx.x - 2048) * 256 + threadIdx.x;
        if (idx >= NB * NDOUT * NR) return;
        int b = idx / (NDOUT * NR);
        int orr = idx - b * (NDOUT * NR);
        int o = orr >> 4, r = orr & 15;
        float s = 0.f;
#pragma unroll
        for (int e = 0; e < NE; e++)
            s += __ldg(&gate[b * NE + e]) * __ldg(&W_up[(size_t)e * NDOUT * NR + orr]);
        size_t off = ((size_t)b * NDOUT + o) * 32;
        g_cb16[off + r] = __float2half_rn(s);
        g_cb16[off + 16 + r] = __float2half_rn(0.f);
    }
}

// ---------------- k_lx: lx[m,0:16] = x @ W_down^T via fp16 mma ----------------
#define LXW 65536                        // 16 n-rows x 2048 k x 2B (fp16 W_down)
#define LX_STG 16384                     // 128 rows x 64 k x 2B (128B rows)
#define LX_SMEM (LXW + 3 * LX_STG)       // 114688
#define LXCK 64
#define LXNCH (NDIN / LXCK)              // 32

__device__ __forceinline__ uint32_t lx_swof(int row, int ch) {   // 128B rows
    return (uint32_t)(row * 128 + ((ch ^ (row & 7)) << 4));
}
__device__ __forceinline__ void lx_issue(uint32_t sb, int s, int c, int rowBase, int tid) {
    uint32_t xs = sb + LXW + s * LX_STG;
#pragma unroll
    for (int j = 0; j < 8; j++) {
        int g = tid + 128 * j;
        int row = g >> 3, ch = g & 7;
        cp16(xs + lx_swof(row, ch),
             g_x16 + (size_t)(rowBase + row) * NDIN + c * LXCK + ch * 8);
    }
}

__global__ void __launch_bounds__(128, 1) k_lx(const float* __restrict__ Wd) {
    extern __shared__ char sm[];
    const uint32_t sb = smem_u32(sm);
    const int tid = threadIdx.x;
    const int w = tid >> 5, lane = tid & 31;
    const int rowBase = blockIdx.x * 128;
    const int lr = lane & 15, lc = lane >> 4;

    // stage W_down fp32 -> fp16 smem [n][2048], 4KB rows, ch^(n&7) swizzle
    for (int idx = tid; idx < 16 * 256; idx += 128) {
        int n = idx >> 8, ch = idx & 255;
        const float* s8 = Wd + (size_t)n * NDIN + ch * 8;
        float4 v0 = *(const float4*)s8;
        float4 v1 = *(const float4*)(s8 + 4);
        H8 o;
        o.h[0] = __float22half2_rn(make_float2(v0.x, v0.y));
        o.h[1] = __float22half2_rn(make_float2(v0.z, v0.w));
        o.h[2] = __float22half2_rn(make_float2(v1.x, v1.y));
        o.h[3] = __float22half2_rn(make_float2(v1.z, v1.w));
        *(uint4*)(sm + n * 4096 + ((ch ^ (n & 7)) << 4)) = o.u;
    }

    float acc[2][2][4];
#pragma unroll
    for (int i = 0; i < 2; i++)
#pragma unroll
        for (int j = 0; j < 2; j++)
#pragma unroll
            for (int q = 0; q < 4; q++) acc[i][j][q] = 0.f;

    lx_issue(sb, 0, 0, rowBase, tid); cp_commit();
    lx_issue(sb, 1, 1, rowBase, tid); cp_commit();

    for (int c = 0; c < LXNCH; c++) {
        cp_wait1();
        __syncthreads();
        if (c + 2 < LXNCH) lx_issue(sb, (c + 2) % 3, c + 2, rowBase, tid);
        cp_commit();
        const uint32_t xs = sb + LXW + (c % 3) * LX_STG;
#pragma unroll
        for (int ks = 0; ks < 4; ks++) {
            // B = W_down rows (n 0-15), k16 = chunks {2K, 2K+1}, K = c*4+ks
            int K = c * 4 + ks;
            uint32_t chB = (uint32_t)(2 * K + lc);
            uint32_t r0, r1, r2, r3;
            LDSM4(r0, r1, r2, r3, sb + lr * 4096 + ((chB ^ (lr & 7)) << 4));
            uint32_t bf0[2] = {r0, r2}, bf1[2] = {r1, r3};
#pragma unroll
            for (int mt = 0; mt < 2; mt++) {
                int row = w * 32 + mt * 16 + lr;
                uint32_t ch = (uint32_t)(ks * 2 + lc);
                uint32_t a[4];
                LDSM4(a[0], a[1], a[2], a[3],
                      xs + row * 128 + ((ch ^ (row & 7)) << 4));
                MMAF16(acc[mt][0], a, bf0[0], bf0[1]);
                MMAF16(acc[mt][1], a, bf1[0], bf1[1]);
            }
        }
        __syncthreads();
    }

    // epilogue: store fp16 lx, zero-pad cols 16-31
#pragma unroll
    for (int mt = 0; mt < 2; mt++) {
        int row = rowBase + w * 32 + mt * 16 + (lane >> 2);
#pragma unroll
        for (int nt = 0; nt < 2; nt++) {
            int col = nt * 8 + (lane & 3) * 2;
            *(__half2*)&g_lx16[(size_t)row * 32 + col] =
                __float22half2_rn(make_float2(acc[mt][nt][0], acc[mt][nt][1]));
            *(__half2*)&g_lx16[(size_t)(row + 8) * 32 + col] =
                __float22half2_rn(make_float2(acc[mt][nt][2], acc[mt][nt][3]));
        }
    }
    {
        int m = rowBase + tid;
        uint4 z = make_uint4(0, 0, 0, 0);
        *(uint4*)&g_lx16[(size_t)m * 32 + 16] = z;
        *(uint4*)&g_lx16[(size_t)m * 32 + 24] = z;
    }
}

// ---------------- main GEMM: fp16 1-pass, 128x128 CTA, 64x64 warp tiles ----------------
__global__ void __launch_bounds__(128, 3) k_gemm(float* __restrict__ out) {
    extern __shared__ char smem[];
    const uint32_t sb0 = smem_u32(smem);
    const int tid = threadIdx.x;
    const int wid = tid >> 5, lane = tid & 31;
    const int wm = wid >> 1, wn = wid & 1;      // 2x2 warp grid, warp tile 64x64
    const int rowBase = blockIdx.y * BM;
    const int colBase = blockIdx.x * BN;
    const int b = blockIdx.y >> 5;              // NS/BM = 32 row-blocks per batch
    const int lr = lane & 15, lc = lane >> 4;

    // fragment bases: 16-row groups, swizzle folded (mt/bp advance = +1024B, ch via XOR)
    uint32_t aOff0, bOff0;
    {
        int ra = wm * 64 + lr;
        aOff0 = (uint32_t)(ra * 64 + (((ra >> 1) & 3) << 4));
        int rb = wn * 64 + lr;
        bOff0 = OF_B + (uint32_t)(rb * 64 + (((rb >> 1) & 3) << 4));
    }

    // loader: 4 A + 4 B cp16 per chunk; j advances 32 rows (swizzle-invariant)
    const int lrow = tid >> 2, lch = tid & 3;
    const uint32_t so0 = swof(lrow, lch);
    const __half* aG = g_x16 + (size_t)(rowBase + lrow) * NDIN + lch * 8;
    const __half* bG = g_w16 + (size_t)(colBase + lrow) * NDIN + lch * 8;
    const __half* aL = g_lx16 + (size_t)(rowBase + lrow) * 32 + lch * 8;
    const __half* bL = g_cb16 + ((size_t)b * NDOUT + colBase + lrow) * 32 + lch * 8;

    float acc[4][8][4];
#pragma unroll
    for (int i = 0; i < 4; i++)
#pragma unroll
        for (int j = 0; j < 8; j++)
#pragma unroll
            for (int q = 0; q < 4; q++) acc[i][j][q] = 0.f;

#pragma unroll
    for (int p = 0; p < 3; p++) {   // prologue: chunks 0,1,2
        uint32_t s = sb0 + p * STAGE_SZ;
#pragma unroll
        for (int j = 0; j < 4; j++) {
            cp16(s + so0 + j * 2048, aG + p * CK + (size_t)j * 32 * NDIN);
            cp16(s + OF_B + so0 + j * 2048, bG + p * CK + (size_t)j * 32 * NDIN);
        }
        cp_commit();
    }

    for (int kc = 0; kc < NCHTOT; kc++) {
        cp_wait2();
        __syncthreads();   // chunk kc ready; all warps done with slot (kc-1)&3

        const int nk = kc + 3;
        if (nk < NCHTOT) {
            uint32_t s = sb0 + (nk & 3) * STAGE_SZ;
            if (nk < NCHUNK) {
#pragma unroll
                for (int j = 0; j < 4; j++) {
                    cp16(s + so0 + j * 2048, aG + nk * CK + (size_t)j * 32 * NDIN);
                    cp16(s + OF_B + so0 + j * 2048, bG + nk * CK + (size_t)j * 32 * NDIN);
                }
            } else {  // LoRA chunk: rows of 32 fp16 = 64B
#pragma unroll
                for (int j = 0; j < 4; j++) {
                    cp16(s + so0 + j * 2048, aL + (size_t)j * 32 * 32);
                    cp16(s + OF_B + so0 + j * 2048, bL + (size_t)j * 32 * 32);
                }
            }
        }
        cp_commit();

        const uint32_t Sb = sb0 + (kc & 3) * STAGE_SZ;
#pragma unroll
        for (int ks = 0; ks < 2; ks++) {             // k16 per step
            const uint32_t cx = (uint32_t)((ks << 1) | lc) << 4;
            // B fragments: 8 n-tiles via 4 LDSM.x4 (16 n-rows x k16 each)
            uint32_t bf[8][2];
#pragma unroll
            for (int bp = 0; bp < 4; bp++) {
                uint32_t r0, r1, r2, r3;
                LDSM4(r0, r1, r2, r3, Sb + ((bOff0 + bp * 1024) ^ cx));
                bf[bp * 2 + 0][0] = r0; bf[bp * 2 + 0][1] = r2;
                bf[bp * 2 + 1][0] = r1; bf[bp * 2 + 1][1] = r3;
            }
            uint32_t a[2][4];
            LDSM4(a[0][0], a[0][1], a[0][2], a[0][3], Sb + (aOff0 ^ cx));
#pragma unroll
            for (int mt = 0; mt < 4; mt++) {
                if (mt < 3) {
                    uint32_t* an = a[(mt + 1) & 1];
                    LDSM4(an[0], an[1], an[2], an[3],
                          Sb + ((aOff0 + (mt + 1) * 1024) ^ cx));
                }
                const uint32_t* ac = a[mt & 1];
#pragma unroll
                for (int nt = 0; nt < 8; nt++)
                    MMAF16(acc[mt][nt], ac, bf[nt][0], bf[nt][1]);
            }
        }
    }

    // ---------------- epilogue ----------------
#pragma unroll
    for (int mt = 0; mt < 4; mt++) {
#pragma unroll
        for (int nt = 0; nt < 8; nt++) {
            int row = rowBase + wm * 64 + mt * 16 + (lane >> 2);
            int col = colBase + wn * 64 + nt * 8 + (lane & 3) * 2;
            *(float2*)&out[(size_t)row * NDOUT + col] =
                make_float2(acc[mt][nt][0], acc[mt][nt][1]);
            *(float2*)&out[(size_t)(row + 8) * NDOUT + col] =
                make_float2(acc[mt][nt][2], acc[mt][nt][3]);
        }
    }
}

// ---------------- launch ----------------
extern "C" void kernel_launch(void* const* d_in, const int* in_sizes, int n_in,
                              void* d_out, int out_size) {
    const float* x      = (const float*)d_in[0];
    const float* gate   = (const float*)d_in[1];
    const float* W_org  = (const float*)d_in[2];
    const float* W_down = (const float*)d_in[3];
    const float* W_up   = (const float*)d_in[4];
    float* out = (float*)d_out;

    cudaFuncSetAttribute(k_gemm, cudaFuncAttributeMaxDynamicSharedMemorySize, SMEM_TOTAL);
    cudaFuncSetAttribute(k_lx, cudaFuncAttributeMaxDynamicSharedMemorySize, LX_SMEM);

    k_cvt_x<<<(size_t)NM * NDIN / 2048, 256>>>(x);
    k_cvt_w_comb<<<2048 + 512, 256>>>(W_org, gate, W_up);
    k_lx<<<NM / 128, 128, LX_SMEM>>>(W_down);

    dim3 grid(NDOUT / BN, NM / BM);   // (16, 128) = 2048 CTAs
    k_gemm<<<grid, 128, SMEM_TOTAL>>>(out);
}